// round 3
// baseline (speedup 1.0000x reference)
#include <cuda_runtime.h>
#include <cstdint>

// Problem constants
#define BATCH 8
#define NPTS  32768
#define MPTS  (NPTS / 4)     // 8192
#define CINCH 128

// FPS kernel config: one cluster of CSZ CTAs per batch
#define CSZ   8
#define TPB   512
#define PPC   (NPTS / CSZ)           // points per CTA = 4096
#define PPT   (PPC / TPB)            // points per thread = 8

// Selected-index scratch (static device global: allocation-free)
__device__ int g_idx[BATCH * MPTS];

// ---------------- helpers ----------------
__device__ __forceinline__ unsigned smem_u32(const void* p) {
    return (unsigned)__cvta_generic_to_shared(p);
}
__device__ __forceinline__ void cluster_sync_() {
    asm volatile("barrier.cluster.arrive.aligned;" ::: "memory");
    asm volatile("barrier.cluster.wait.aligned;" ::: "memory");
}
__device__ __forceinline__ unsigned mapa_rank(unsigned local_addr, int r) {
    unsigned ret;
    asm("mapa.shared::cluster.u32 %0, %1, %2;" : "=r"(ret) : "r"(local_addr), "r"(r));
    return ret;
}
__device__ __forceinline__ void st_cluster_f32(unsigned addr, float v) {
    asm volatile("st.shared::cluster.f32 [%0], %1;" :: "r"(addr), "f"(v) : "memory");
}
__device__ __forceinline__ void st_cluster_s32(unsigned addr, int v) {
    asm volatile("st.shared::cluster.s32 [%0], %1;" :: "r"(addr), "r"(v) : "memory");
}
__device__ __forceinline__ unsigned cluster_rank_() {
    unsigned r;
    asm("mov.u32 %0, %%cluster_ctarank;" : "=r"(r));
    return r;
}

// Reference-exact squared distance, variant F:
// sum emitted as the tree (dx^2 + dy^2) + dz^2 with LLVM fadd(fmul,fmul)
// contraction fusing the FIRST operand:
//   inner = fma(dx,dx, rn(dy*dy)); d = fma(dz,dz, inner)
__device__ __forceinline__ float sqdist_ref(float dx, float dy, float dz) {
    float acc = __fmul_rn(dy, dy);
    acc = __fmaf_rn(dx, dx, acc);
    acc = __fmaf_rn(dz, dz, acc);
    return acc;
}

// -------------- FPS kernel ---------------
// Grid: BATCH*CSZ blocks, cluster dims (CSZ,1,1). Each cluster = one batch.
// Coordinates and running min-distances live in registers (8 pts/thread).
__global__ void __launch_bounds__(TPB, 1) __cluster_dims__(CSZ, 1, 1)
fps_kernel(const float* __restrict__ xyz)
{
    const int rank  = (int)cluster_rank_();
    const int batch = blockIdx.x / CSZ;
    const float* __restrict__ xb = xyz + (size_t)batch * 3 * NPTS;
    const int tid  = threadIdx.x;
    const int base = rank * PPC;

    // partials: 16 warps
    __shared__ float s_pd[16], s_px[16], s_py[16], s_pz[16];
    __shared__ int   s_pi[16];
    // cross-CTA gather slots (used on rank 0 only)
    __shared__ float s_sd[CSZ], s_sx[CSZ], s_sy[CSZ], s_sz[CSZ];
    __shared__ int   s_si[CSZ];
    // broadcast answer: centroid coords for next iteration
    __shared__ float s_ans[3];

    // register-resident point data
    float px[PPT], py[PPT], pz[PPT], dd[PPT];
#pragma unroll
    for (int j = 0; j < PPT; j++) {
        int i = base + j * TPB + tid;
        px[j] = xb[i];
        py[j] = xb[NPTS + i];
        pz[j] = xb[2 * NPTS + i];
        dd[j] = 1e10f;
    }

    if (tid == 0) {
        // initial farthest = point 0 (reference uses fixed seed point 0)
        s_ans[0] = xb[0];
        s_ans[1] = xb[NPTS];
        s_ans[2] = xb[2 * NPTS];
        if (rank == 0) g_idx[batch * MPTS] = 0;
    }
    cluster_sync_();

    for (int it = 1; it < MPTS; ++it) {
        const float cx = s_ans[0], cy = s_ans[1], cz = s_ans[2];

        float bd = -1.0f, bx = 0.0f, by = 0.0f, bz = 0.0f;
        int bi = 0;
#pragma unroll
        for (int j = 0; j < PPT; j++) {
            float dx = __fsub_rn(px[j], cx);
            float dy = __fsub_rn(py[j], cy);
            float dz = __fsub_rn(pz[j], cz);
            float d  = sqdist_ref(dx, dy, dz);
            float nd = fminf(dd[j], d);
            dd[j] = nd;
            // strict > keeps earliest (lowest) index within this thread
            if (nd > bd) {
                bd = nd;
                bi = base + j * TPB + tid;
                bx = px[j]; by = py[j]; bz = pz[j];
            }
        }

        // warp reduce (argmax, ties -> lowest index)
        const unsigned FULL = 0xffffffffu;
#pragma unroll
        for (int off = 16; off > 0; off >>= 1) {
            float od = __shfl_down_sync(FULL, bd, off);
            int   oi = __shfl_down_sync(FULL, bi, off);
            float ox = __shfl_down_sync(FULL, bx, off);
            float oy = __shfl_down_sync(FULL, by, off);
            float oz = __shfl_down_sync(FULL, bz, off);
            if (od > bd || (od == bd && oi < bi)) {
                bd = od; bi = oi; bx = ox; by = oy; bz = oz;
            }
        }

        const int w = tid >> 5, l = tid & 31;
        if (l == 0) {
            s_pd[w] = bd; s_pi[w] = bi;
            s_px[w] = bx; s_py[w] = by; s_pz[w] = bz;
        }
        __syncthreads();

        if (w == 0) {
            int sl = l & 15;
            bd = (l < 16) ? s_pd[sl] : -1.0f;
            bi = (l < 16) ? s_pi[sl] : 0x7fffffff;
            bx = s_px[sl]; by = s_py[sl]; bz = s_pz[sl];
#pragma unroll
            for (int off = 8; off > 0; off >>= 1) {
                float od = __shfl_down_sync(FULL, bd, off);
                int   oi = __shfl_down_sync(FULL, bi, off);
                float ox = __shfl_down_sync(FULL, bx, off);
                float oy = __shfl_down_sync(FULL, by, off);
                float oz = __shfl_down_sync(FULL, bz, off);
                if (od > bd || (od == bd && oi < bi)) {
                    bd = od; bi = oi; bx = ox; by = oy; bz = oz;
                }
            }
            if (l == 0) {
                // push CTA best into rank0's gather slot [rank]
                unsigned ad = mapa_rank(smem_u32(&s_sd[rank]), 0);
                unsigned ai = mapa_rank(smem_u32(&s_si[rank]), 0);
                unsigned ax = mapa_rank(smem_u32(&s_sx[rank]), 0);
                unsigned ay = mapa_rank(smem_u32(&s_sy[rank]), 0);
                unsigned az = mapa_rank(smem_u32(&s_sz[rank]), 0);
                st_cluster_f32(ad, bd);
                st_cluster_s32(ai, bi);
                st_cluster_f32(ax, bx);
                st_cluster_f32(ay, by);
                st_cluster_f32(az, bz);
            }
        }

        cluster_sync_();  // gather slots visible on rank 0

        if (rank == 0 && tid == 0) {
            float wd = s_sd[0], wx = s_sx[0], wy = s_sy[0], wz = s_sz[0];
            int   wi = s_si[0];
#pragma unroll
            for (int r = 1; r < CSZ; r++) {
                float od = s_sd[r];
                int   oi = s_si[r];
                if (od > wd || (od == wd && oi < wi)) {
                    wd = od; wi = oi;
                    wx = s_sx[r]; wy = s_sy[r]; wz = s_sz[r];
                }
            }
            g_idx[batch * MPTS + it] = wi;
            // scatter winner coords to every rank's s_ans
            unsigned ansLocal = smem_u32(&s_ans[0]);
#pragma unroll
            for (int r = 0; r < CSZ; r++) {
                unsigned ra = mapa_rank(ansLocal, r);
                st_cluster_f32(ra,     wx);
                st_cluster_f32(ra + 4, wy);
                st_cluster_f32(ra + 8, wz);
            }
        }

        cluster_sync_();  // answer visible everywhere
    }
}

// -------------- gather kernel ---------------
// out = concat( sampled_xyz [B,3,M], sampled_feature [B,Cin,M] )
__global__ void gather_kernel(const float* __restrict__ xyz,
                              const float* __restrict__ feat,
                              float* __restrict__ out)
{
    const long P1  = (long)BATCH * 3 * MPTS;
    const long TOT = P1 + (long)BATCH * CINCH * MPTS;
    long gi = (long)blockIdx.x * blockDim.x + threadIdx.x;
    if (gi >= TOT) return;

    if (gi < P1) {
        int m = (int)(gi % MPTS);
        int c = (int)((gi / MPTS) % 3);
        int b = (int)(gi / ((long)3 * MPTS));
        int idx = g_idx[b * MPTS + m];
        out[gi] = xyz[(size_t)b * 3 * NPTS + (size_t)c * NPTS + idx];
    } else {
        long gj = gi - P1;
        int m = (int)(gj % MPTS);
        int c = (int)((gj / MPTS) % CINCH);
        int b = (int)(gj / ((long)CINCH * MPTS));
        int idx = g_idx[b * MPTS + m];
        out[gi] = feat[(size_t)b * CINCH * NPTS + (size_t)c * NPTS + idx];
    }
}

extern "C" void kernel_launch(void* const* d_in, const int* in_sizes, int n_in,
                              void* d_out, int out_size)
{
    // Defensive: pick xyz by element count (B*3*N = 786432)
    const float* xyz;
    const float* feat;
    if (in_sizes[0] == BATCH * 3 * NPTS) {
        xyz  = (const float*)d_in[0];
        feat = (const float*)d_in[1];
    } else {
        xyz  = (const float*)d_in[1];
        feat = (const float*)d_in[0];
    }
    float* out = (float*)d_out;

    fps_kernel<<<BATCH * CSZ, TPB>>>(xyz);

    const long tot = (long)BATCH * (3 + CINCH) * MPTS;
    const int thr = 256;
    const unsigned blocks = (unsigned)((tot + thr - 1) / thr);
    gather_kernel<<<blocks, thr>>>(xyz, feat, out);
}